// round 1
// baseline (speedup 1.0000x reference)
#include <cuda_runtime.h>
#include <math.h>

// Problem constants
#define BSZ 2
#define SSZ 2048
#define DSZ 1024
#define HN  16
#define DK  64
#define MROWS (BSZ*SSZ)      // 4096
#define NPAIR 32             // DK/2

// Scratch (device globals — no allocation allowed)
__device__ float g_Q[BSZ*HN*SSZ*DK];     // [B,H,S,dk]
__device__ float g_K[BSZ*HN*SSZ*DK];
__device__ float g_V[BSZ*HN*SSZ*DK];
__device__ float g_O[BSZ*SSZ*DSZ];       // [B,S,D]
__device__ float g_cos[SSZ*NPAIR];
__device__ float g_sin[SSZ*NPAIR];

// ---------------------------------------------------------------------------
// RoPE table: ang = s * 10000^(-p/32), computed in double for accuracy.
// ---------------------------------------------------------------------------
__global__ void rope_table_kernel() {
    int i = blockIdx.x * blockDim.x + threadIdx.x;
    if (i >= SSZ * NPAIR) return;
    int s = i >> 5, p = i & 31;
    double ang = (double)s * exp(-(double)p * (9.210340371976184 / 32.0));
    g_cos[i] = (float)cos(ang);
    g_sin[i] = (float)sin(ang);
}

// ---------------------------------------------------------------------------
// In-place RoPE on g_Q and g_K. One thread per (b,h,s,pair).
// ---------------------------------------------------------------------------
__global__ void rope_apply_kernel() {
    int idx = blockIdx.x * blockDim.x + threadIdx.x;
    if (idx >= BSZ*HN*SSZ*NPAIR) return;
    int p = idx & 31;
    int s = (idx >> 5) & (SSZ - 1);
    float ca = g_cos[(s << 5) | p];
    float sa = g_sin[(s << 5) | p];
    int off = ((idx >> 5) << 6) | (p << 1);
    float q1 = g_Q[off], q2 = g_Q[off + 1];
    g_Q[off]     = q1 * ca - q2 * sa;
    g_Q[off + 1] = q1 * sa + q2 * ca;
    float k1 = g_K[off], k2 = g_K[off + 1];
    g_K[off]     = k1 * ca - k2 * sa;
    g_K[off + 1] = k1 * sa + k2 * ca;
}

// ---------------------------------------------------------------------------
// Shared NT-SGEMM tile body: C[128x128] += A[128xK] * B[128xK]^T
// 256 threads, 8x8 per thread, BK=16, K=1024, both operands K-major.
// ---------------------------------------------------------------------------
__device__ __forceinline__ void gemm_tile_body(
    const float* __restrict__ A, const float* __restrict__ Bm,
    int m0, int n0, float (&acc)[8][8],
    float (*As)[132], float (*Bs)[132])
{
    const int tid = threadIdx.x;
    const int lr = tid >> 2;
    const int lc = (tid & 3) << 2;
    const int tx = tid & 15, ty = tid >> 4;

    for (int kb = 0; kb < 1024; kb += 16) {
        float4 a0 = *(const float4*)&A [(m0 + lr)      * 1024 + kb + lc];
        float4 a1 = *(const float4*)&A [(m0 + lr + 64) * 1024 + kb + lc];
        float4 b0 = *(const float4*)&Bm[(n0 + lr)      * 1024 + kb + lc];
        float4 b1 = *(const float4*)&Bm[(n0 + lr + 64) * 1024 + kb + lc];
        __syncthreads();
        As[lc+0][lr] = a0.x; As[lc+1][lr] = a0.y; As[lc+2][lr] = a0.z; As[lc+3][lr] = a0.w;
        As[lc+0][lr+64] = a1.x; As[lc+1][lr+64] = a1.y; As[lc+2][lr+64] = a1.z; As[lc+3][lr+64] = a1.w;
        Bs[lc+0][lr] = b0.x; Bs[lc+1][lr] = b0.y; Bs[lc+2][lr] = b0.z; Bs[lc+3][lr] = b0.w;
        Bs[lc+0][lr+64] = b1.x; Bs[lc+1][lr+64] = b1.y; Bs[lc+2][lr+64] = b1.z; Bs[lc+3][lr+64] = b1.w;
        __syncthreads();
#pragma unroll
        for (int k = 0; k < 16; k++) {
            float a[8], b[8];
            float4 t;
            t = *(const float4*)&As[k][ty*8];     a[0]=t.x; a[1]=t.y; a[2]=t.z; a[3]=t.w;
            t = *(const float4*)&As[k][ty*8 + 4]; a[4]=t.x; a[5]=t.y; a[6]=t.z; a[7]=t.w;
            t = *(const float4*)&Bs[k][tx*8];     b[0]=t.x; b[1]=t.y; b[2]=t.z; b[3]=t.w;
            t = *(const float4*)&Bs[k][tx*8 + 4]; b[4]=t.x; b[5]=t.y; b[6]=t.z; b[7]=t.w;
#pragma unroll
            for (int i = 0; i < 8; i++)
#pragma unroll
                for (int j = 0; j < 8; j++)
                    acc[i][j] = fmaf(a[i], b[j], acc[i][j]);
        }
    }
}

// QKV projection: out = x @ W^T, scattered to [B,H,S,dk]. blockIdx.z picks Q/K/V.
__global__ __launch_bounds__(256) void gemm_qkv_kernel(
    const float* __restrict__ x,
    const float* __restrict__ Wq,
    const float* __restrict__ Wk,
    const float* __restrict__ Wv)
{
    const float* W = blockIdx.z == 0 ? Wq : (blockIdx.z == 1 ? Wk : Wv);
    float* dst     = blockIdx.z == 0 ? g_Q : (blockIdx.z == 1 ? g_K : g_V);

    __shared__ float As[16][132];
    __shared__ float Bs[16][132];

    const int tx = threadIdx.x & 15, ty = threadIdx.x >> 4;
    const int m0 = blockIdx.y * 128, n0 = blockIdx.x * 128;

    float acc[8][8];
#pragma unroll
    for (int i = 0; i < 8; i++)
#pragma unroll
        for (int j = 0; j < 8; j++) acc[i][j] = 0.f;

    gemm_tile_body(x, W, m0, n0, acc, As, Bs);

#pragma unroll
    for (int i = 0; i < 8; i++) {
        int m = m0 + ty * 8 + i;
        int b = m >> 11, s = m & (SSZ - 1);
#pragma unroll
        for (int j = 0; j < 8; j++) {
            int n = n0 + tx * 8 + j;
            int h = n >> 6, c = n & 63;
            dst[(((b << 4) | h) * SSZ + s) * DK + c] = acc[i][j];
        }
    }
}

// Output projection: out = g_O @ Wo^T, plain [4096,1024].
__global__ __launch_bounds__(256) void gemm_out_kernel(
    const float* __restrict__ Wo, float* __restrict__ C)
{
    __shared__ float As[16][132];
    __shared__ float Bs[16][132];

    const int tx = threadIdx.x & 15, ty = threadIdx.x >> 4;
    const int m0 = blockIdx.y * 128, n0 = blockIdx.x * 128;

    float acc[8][8];
#pragma unroll
    for (int i = 0; i < 8; i++)
#pragma unroll
        for (int j = 0; j < 8; j++) acc[i][j] = 0.f;

    gemm_tile_body(g_O, Wo, m0, n0, acc, As, Bs);

#pragma unroll
    for (int i = 0; i < 8; i++)
#pragma unroll
        for (int j = 0; j < 8; j++)
            C[(m0 + ty * 8 + i) * 1024 + n0 + tx * 8 + j] = acc[i][j];
}

// ---------------------------------------------------------------------------
// SIMT flash attention: one CTA = one (b,h) x 64-query block.
// BQ=BK=64, dk=64, online softmax, causal block skipping.
// Thread tile: rows tr*4+i, cols tc+16*j (pad-65 keeps LDS conflict-free).
// ---------------------------------------------------------------------------
__global__ __launch_bounds__(256) void attn_kernel() {
    extern __shared__ float sm[];
    float* sQ = sm;
    float* sK = sm + 64 * 65;
    float* sV = sm + 2 * 64 * 65;
    float* sP = sm + 3 * 64 * 65;

    const int tid = threadIdx.x;
    const int tr = tid >> 4;   // 0..15 -> rows tr*4..tr*4+3
    const int tc = tid & 15;   // 0..15 -> cols tc, tc+16, tc+32, tc+48
    const int qb = (int)gridDim.x - 1 - (int)blockIdx.x;  // heavy CTAs first
    const int bh = blockIdx.y;
    const float* Qg = g_Q + (size_t)bh * SSZ * DK;
    const float* Kg = g_K + (size_t)bh * SSZ * DK;
    const float* Vg = g_V + (size_t)bh * SSZ * DK;

    // load Q block, fold in 1/sqrt(dk)
#pragma unroll
    for (int t = 0; t < 4; t++) {
        int e = t * 256 + tid;
        int row = e >> 4;
        int col = (e & 15) << 2;
        float4 v = *(const float4*)&Qg[(qb * 64 + row) * DK + col];
        sQ[row * 65 + col + 0] = v.x * 0.125f;
        sQ[row * 65 + col + 1] = v.y * 0.125f;
        sQ[row * 65 + col + 2] = v.z * 0.125f;
        sQ[row * 65 + col + 3] = v.w * 0.125f;
    }

    float m_run[4], l_run[4], acc[4][4];
#pragma unroll
    for (int i = 0; i < 4; i++) {
        m_run[i] = -1e30f; l_run[i] = 0.f;
#pragma unroll
        for (int j = 0; j < 4; j++) acc[i][j] = 0.f;
    }

    for (int kb = 0; kb <= qb; kb++) {
        __syncthreads();   // previous-iter sP/sV reads done
#pragma unroll
        for (int t = 0; t < 4; t++) {
            int e = t * 256 + tid;
            int row = e >> 4;
            int col = (e & 15) << 2;
            float4 kv = *(const float4*)&Kg[(kb * 64 + row) * DK + col];
            float4 vv = *(const float4*)&Vg[(kb * 64 + row) * DK + col];
            sK[row * 65 + col + 0] = kv.x; sK[row * 65 + col + 1] = kv.y;
            sK[row * 65 + col + 2] = kv.z; sK[row * 65 + col + 3] = kv.w;
            sV[row * 65 + col + 0] = vv.x; sV[row * 65 + col + 1] = vv.y;
            sV[row * 65 + col + 2] = vv.z; sV[row * 65 + col + 3] = vv.w;
        }
        __syncthreads();

        // S = Q K^T (64x64x64)
        float sv[4][4];
#pragma unroll
        for (int i = 0; i < 4; i++)
#pragma unroll
            for (int j = 0; j < 4; j++) sv[i][j] = 0.f;

#pragma unroll 8
        for (int k = 0; k < 64; k++) {
            float q0 = sQ[(tr * 4 + 0) * 65 + k];
            float q1 = sQ[(tr * 4 + 1) * 65 + k];
            float q2 = sQ[(tr * 4 + 2) * 65 + k];
            float q3 = sQ[(tr * 4 + 3) * 65 + k];
            float k0 = sK[(tc +  0) * 65 + k];
            float k1 = sK[(tc + 16) * 65 + k];
            float k2 = sK[(tc + 32) * 65 + k];
            float k3 = sK[(tc + 48) * 65 + k];
            sv[0][0] = fmaf(q0, k0, sv[0][0]); sv[0][1] = fmaf(q0, k1, sv[0][1]);
            sv[0][2] = fmaf(q0, k2, sv[0][2]); sv[0][3] = fmaf(q0, k3, sv[0][3]);
            sv[1][0] = fmaf(q1, k0, sv[1][0]); sv[1][1] = fmaf(q1, k1, sv[1][1]);
            sv[1][2] = fmaf(q1, k2, sv[1][2]); sv[1][3] = fmaf(q1, k3, sv[1][3]);
            sv[2][0] = fmaf(q2, k0, sv[2][0]); sv[2][1] = fmaf(q2, k1, sv[2][1]);
            sv[2][2] = fmaf(q2, k2, sv[2][2]); sv[2][3] = fmaf(q2, k3, sv[2][3]);
            sv[3][0] = fmaf(q3, k0, sv[3][0]); sv[3][1] = fmaf(q3, k1, sv[3][1]);
            sv[3][2] = fmaf(q3, k2, sv[3][2]); sv[3][3] = fmaf(q3, k3, sv[3][3]);
        }

        // causal mask on diagonal block
        if (kb == qb) {
#pragma unroll
            for (int i = 0; i < 4; i++)
#pragma unroll
                for (int j = 0; j < 4; j++)
                    if (tc + 16 * j > tr * 4 + i) sv[i][j] = -1e30f;
        }

        // online softmax per row (row group = 16 lanes with same tr)
#pragma unroll
        for (int i = 0; i < 4; i++) {
            float mx = fmaxf(fmaxf(sv[i][0], sv[i][1]), fmaxf(sv[i][2], sv[i][3]));
#pragma unroll
            for (int o = 8; o > 0; o >>= 1)
                mx = fmaxf(mx, __shfl_xor_sync(0xffffffffu, mx, o));
            float mnew = fmaxf(m_run[i], mx);
            float corr = expf(m_run[i] - mnew);
            float rs = 0.f;
#pragma unroll
            for (int j = 0; j < 4; j++) {
                float p = expf(sv[i][j] - mnew);
                sP[(tr * 4 + i) * 65 + tc + 16 * j] = p;
                rs += p;
            }
#pragma unroll
            for (int o = 8; o > 0; o >>= 1)
                rs += __shfl_xor_sync(0xffffffffu, rs, o);
            l_run[i] = l_run[i] * corr + rs;
            m_run[i] = mnew;
#pragma unroll
            for (int j = 0; j < 4; j++) acc[i][j] *= corr;
        }
        __syncthreads();

        // O += P V (64x64x64)
#pragma unroll 8
        for (int c = 0; c < 64; c++) {
            float p0 = sP[(tr * 4 + 0) * 65 + c];
            float p1 = sP[(tr * 4 + 1) * 65 + c];
            float p2 = sP[(tr * 4 + 2) * 65 + c];
            float p3 = sP[(tr * 4 + 3) * 65 + c];
            float v0 = sV[c * 65 + tc +  0];
            float v1 = sV[c * 65 + tc + 16];
            float v2 = sV[c * 65 + tc + 32];
            float v3 = sV[c * 65 + tc + 48];
            acc[0][0] = fmaf(p0, v0, acc[0][0]); acc[0][1] = fmaf(p0, v1, acc[0][1]);
            acc[0][2] = fmaf(p0, v2, acc[0][2]); acc[0][3] = fmaf(p0, v3, acc[0][3]);
            acc[1][0] = fmaf(p1, v0, acc[1][0]); acc[1][1] = fmaf(p1, v1, acc[1][1]);
            acc[1][2] = fmaf(p1, v2, acc[1][2]); acc[1][3] = fmaf(p1, v3, acc[1][3]);
            acc[2][0] = fmaf(p2, v0, acc[2][0]); acc[2][1] = fmaf(p2, v1, acc[2][1]);
            acc[2][2] = fmaf(p2, v2, acc[2][2]); acc[2][3] = fmaf(p2, v3, acc[2][3]);
            acc[3][0] = fmaf(p3, v0, acc[3][0]); acc[3][1] = fmaf(p3, v1, acc[3][1]);
            acc[3][2] = fmaf(p3, v2, acc[3][2]); acc[3][3] = fmaf(p3, v3, acc[3][3]);
        }
    }

    // epilogue: normalize, transpose to [B,S,D]
    const int b = bh >> 4;
    const int h = bh & 15;
#pragma unroll
    for (int i = 0; i < 4; i++) {
        int q = qb * 64 + tr * 4 + i;
        float inv = 1.f / l_run[i];
#pragma unroll
        for (int j = 0; j < 4; j++)
            g_O[((size_t)b * SSZ + q) * DSZ + h * DK + tc + 16 * j] = acc[i][j] * inv;
    }
}

// ---------------------------------------------------------------------------
extern "C" void kernel_launch(void* const* d_in, const int* in_sizes, int n_in,
                              void* d_out, int out_size) {
    (void)in_sizes; (void)n_in; (void)out_size;
    const float* x  = (const float*)d_in[0];
    const float* Wq = (const float*)d_in[1];
    const float* Wk = (const float*)d_in[2];
    const float* Wv = (const float*)d_in[3];
    const float* Wo = (const float*)d_in[4];
    float* out = (float*)d_out;

    rope_table_kernel<<<(SSZ * NPAIR + 255) / 256, 256>>>();
    gemm_qkv_kernel<<<dim3(8, 32, 3), 256>>>(x, Wq, Wk, Wv);
    rope_apply_kernel<<<(BSZ * HN * SSZ * NPAIR + 255) / 256, 256>>>();

    const int attn_smem = 4 * 64 * 65 * (int)sizeof(float);  // 66560 B
    cudaFuncSetAttribute(attn_kernel, cudaFuncAttributeMaxDynamicSharedMemorySize, attn_smem);
    attn_kernel<<<dim3(SSZ / 64, BSZ * HN), 256, attn_smem>>>();

    gemm_out_kernel<<<dim3(8, 32), 256>>>(Wo, out);
}

// round 2
// speedup vs baseline: 2.9536x; 2.9536x over previous
#include <cuda_runtime.h>
#include <math.h>

#define BSZ 2
#define SSZ 2048
#define DSZ 1024
#define HN  16
#define DK  64
#define NPAIR 32

__device__ float g_Q[BSZ*HN*SSZ*DK];
__device__ float g_K[BSZ*HN*SSZ*DK];
__device__ float g_V[BSZ*HN*SSZ*DK];
__device__ float g_O[BSZ*SSZ*DSZ];
__device__ float g_cos[SSZ*NPAIR];
__device__ float g_sin[SSZ*NPAIR];

// ---------------------------------------------------------------------------
// tf32 helpers
// ---------------------------------------------------------------------------
__device__ __forceinline__ unsigned f2tf(float f) {
    unsigned u;
    asm("cvt.rna.tf32.f32 %0, %1;" : "=r"(u) : "f"(f));
    return u;
}
__device__ __forceinline__ float f2tff(float f) { return __uint_as_float(f2tf(f)); }

__device__ __forceinline__ void mma8(float* c, const unsigned* a, const unsigned* b) {
    asm volatile(
        "mma.sync.aligned.m16n8k8.row.col.f32.tf32.tf32.f32 "
        "{%0,%1,%2,%3}, {%4,%5,%6,%7}, {%8,%9}, {%0,%1,%2,%3};"
        : "+f"(c[0]), "+f"(c[1]), "+f"(c[2]), "+f"(c[3])
        : "r"(a[0]), "r"(a[1]), "r"(a[2]), "r"(a[3]), "r"(b[0]), "r"(b[1]));
}

// ---------------------------------------------------------------------------
// RoPE table + apply (unchanged from R1)
// ---------------------------------------------------------------------------
__global__ void rope_table_kernel() {
    int i = blockIdx.x * blockDim.x + threadIdx.x;
    if (i >= SSZ * NPAIR) return;
    int s = i >> 5, p = i & 31;
    double ang = (double)s * exp(-(double)p * (9.210340371976184 / 32.0));
    g_cos[i] = (float)cos(ang);
    g_sin[i] = (float)sin(ang);
}

__global__ void rope_apply_kernel() {
    int idx = blockIdx.x * blockDim.x + threadIdx.x;
    if (idx >= BSZ*HN*SSZ*NPAIR) return;
    int p = idx & 31;
    int s = (idx >> 5) & (SSZ - 1);
    float ca = g_cos[(s << 5) | p];
    float sa = g_sin[(s << 5) | p];
    int off = ((idx >> 5) << 6) | (p << 1);
    float q1 = g_Q[off], q2 = g_Q[off + 1];
    g_Q[off]     = q1 * ca - q2 * sa;
    g_Q[off + 1] = q1 * sa + q2 * ca;
    float k1 = g_K[off], k2 = g_K[off + 1];
    g_K[off]     = k1 * ca - k2 * sa;
    g_K[off + 1] = k1 * sa + k2 * ca;
}

// ---------------------------------------------------------------------------
// tf32 NT-GEMM body: C[128x128] = A[128x1024] * W[128x1024]^T
// 256 thr / 8 warps, warp tile 32x64, BK=16, double-buffered smem stride 20
// (banks 20g+t mod 32 form a perfect 32-cover -> conflict-free frag loads).
// ---------------------------------------------------------------------------
#define GST 20

__device__ __forceinline__ void gemm_body(
    const float* __restrict__ A, const float* __restrict__ W,
    int m0, int n0, float (&acc)[2][8][4],
    float (*As)[128*GST], float (*Bs)[128*GST])
{
    const int tid = threadIdx.x;
    const int lane = tid & 31;
    const int g = lane >> 2, t = lane & 3;
    const int wid = tid >> 5;
    const int wm = (wid & 3) * 32, wn = (wid >> 2) * 64;
    const int row = tid >> 2, c4 = (tid & 3) << 2;

    float4 r0, r1, r2, r3;

    auto ldg = [&](int kb) {
        r0 = *(const float4*)(A + (size_t)(m0 + row)      * 1024 + kb + c4);
        r1 = *(const float4*)(A + (size_t)(m0 + row + 64) * 1024 + kb + c4);
        r2 = *(const float4*)(W + (size_t)(n0 + row)      * 1024 + kb + c4);
        r3 = *(const float4*)(W + (size_t)(n0 + row + 64) * 1024 + kb + c4);
    };
    auto cv4 = [&](float4 v) {
        float4 o;
        o.x = f2tff(v.x); o.y = f2tff(v.y); o.z = f2tff(v.z); o.w = f2tff(v.w);
        return o;
    };
    auto sts = [&](int bi) {
        *(float4*)&As[bi][(row)      * GST + c4] = cv4(r0);
        *(float4*)&As[bi][(row + 64) * GST + c4] = cv4(r1);
        *(float4*)&Bs[bi][(row)      * GST + c4] = cv4(r2);
        *(float4*)&Bs[bi][(row + 64) * GST + c4] = cv4(r3);
    };
    auto comp = [&](int bi) {
#pragma unroll
        for (int ks = 0; ks < 2; ks++) {
            const int k0 = ks * 8;
            unsigned af[2][4], bf[8][2];
#pragma unroll
            for (int mt = 0; mt < 2; mt++) {
                const float* p = &As[bi][(wm + mt*16 + g) * GST + k0 + t];
                af[mt][0] = __float_as_uint(p[0]);
                af[mt][1] = __float_as_uint(p[8*GST]);
                af[mt][2] = __float_as_uint(p[4]);
                af[mt][3] = __float_as_uint(p[8*GST + 4]);
            }
#pragma unroll
            for (int nt = 0; nt < 8; nt++) {
                const float* p = &Bs[bi][(wn + nt*8 + g) * GST + k0 + t];
                bf[nt][0] = __float_as_uint(p[0]);
                bf[nt][1] = __float_as_uint(p[4]);
            }
#pragma unroll
            for (int mt = 0; mt < 2; mt++)
#pragma unroll
                for (int nt = 0; nt < 8; nt++)
                    mma8(acc[mt][nt], af[mt], bf[nt]);
        }
    };

    ldg(0);
    sts(0);
    __syncthreads();
    for (int kb = 0; kb < 64; kb++) {
        if (kb + 1 < 64) ldg((kb + 1) * 16);
        comp(kb & 1);
        if (kb + 1 < 64) {
            sts((kb + 1) & 1);
            __syncthreads();
        }
    }
}

// QKV projection, scattered to [B,H,S,dk]
__global__ __launch_bounds__(256) void gemm_qkv_kernel(
    const float* __restrict__ x,
    const float* __restrict__ Wq,
    const float* __restrict__ Wk,
    const float* __restrict__ Wv)
{
    __shared__ float As[2][128*GST];
    __shared__ float Bs[2][128*GST];
    const float* W = blockIdx.z == 0 ? Wq : (blockIdx.z == 1 ? Wk : Wv);
    float* dst     = blockIdx.z == 0 ? g_Q : (blockIdx.z == 1 ? g_K : g_V);

    const int tid = threadIdx.x;
    const int lane = tid & 31;
    const int g = lane >> 2, t = lane & 3;
    const int wid = tid >> 5;
    const int wm = (wid & 3) * 32, wn = (wid >> 2) * 64;
    const int m0 = blockIdx.y * 128, n0 = blockIdx.x * 128;

    float acc[2][8][4];
#pragma unroll
    for (int i = 0; i < 2; i++)
#pragma unroll
        for (int j = 0; j < 8; j++)
#pragma unroll
            for (int k = 0; k < 4; k++) acc[i][j][k] = 0.f;

    gemm_body(x, W, m0, n0, acc, As, Bs);

#pragma unroll
    for (int mt = 0; mt < 2; mt++) {
        int m = m0 + wm + mt * 16 + g;
        int b = m >> 11, s = m & (SSZ - 1);
#pragma unroll
        for (int nt = 0; nt < 8; nt++) {
            int n = n0 + wn + nt * 8 + 2 * t;
            int h = n >> 6, c = n & 63;
            float* base = dst + (((size_t)b * HN + h) * SSZ) * DK + c;
            *(float2*)(base + (size_t)s * DK)       = make_float2(acc[mt][nt][0], acc[mt][nt][1]);
            *(float2*)(base + (size_t)(s + 8) * DK) = make_float2(acc[mt][nt][2], acc[mt][nt][3]);
        }
    }
}

// Output projection: out = g_O @ Wo^T
__global__ __launch_bounds__(256) void gemm_out_kernel(
    const float* __restrict__ Wo, float* __restrict__ C)
{
    __shared__ float As[2][128*GST];
    __shared__ float Bs[2][128*GST];

    const int tid = threadIdx.x;
    const int lane = tid & 31;
    const int g = lane >> 2, t = lane & 3;
    const int wid = tid >> 5;
    const int wm = (wid & 3) * 32, wn = (wid >> 2) * 64;
    const int m0 = blockIdx.y * 128, n0 = blockIdx.x * 128;

    float acc[2][8][4];
#pragma unroll
    for (int i = 0; i < 2; i++)
#pragma unroll
        for (int j = 0; j < 8; j++)
#pragma unroll
            for (int k = 0; k < 4; k++) acc[i][j][k] = 0.f;

    gemm_body(g_O, Wo, m0, n0, acc, As, Bs);

#pragma unroll
    for (int mt = 0; mt < 2; mt++) {
        int m = m0 + wm + mt * 16 + g;
#pragma unroll
        for (int nt = 0; nt < 8; nt++) {
            int n = n0 + wn + nt * 8 + 2 * t;
            *(float2*)(C + (size_t)m * 1024 + n)       = make_float2(acc[mt][nt][0], acc[mt][nt][1]);
            *(float2*)(C + (size_t)(m + 8) * 1024 + n) = make_float2(acc[mt][nt][2], acc[mt][nt][3]);
        }
    }
}

// ---------------------------------------------------------------------------
// tf32 flash attention: 128 thr / 4 warps, BQ=BK=64, dk=64.
// Warp w owns q rows w*16..w*16+15. Q fragments cached in registers.
// smem: sQP[64][72] (Q staging, then P), sK[64][68], sV[64][72].
// All fragment loads and P stores are bank-conflict-free by stride choice.
// ---------------------------------------------------------------------------
__global__ __launch_bounds__(128) void attn_kernel() {
    extern __shared__ float sm[];
    float* sQP = sm;                       // [64][72]
    float* sK  = sm + 64*72;               // [64][68]
    float* sV  = sm + 64*72 + 64*68;       // [64][72]

    const int tid = threadIdx.x;
    const int w = tid >> 5;
    const int lane = tid & 31;
    const int g = lane >> 2, t = lane & 3;
    const int qb = (int)gridDim.x - 1 - (int)blockIdx.x;   // heavy CTAs first
    const int bh = blockIdx.y;
    const float* Qg = g_Q + (size_t)bh * SSZ * DK;
    const float* Kg = g_K + (size_t)bh * SSZ * DK;
    const float* Vg = g_V + (size_t)bh * SSZ * DK;

    // stage Q (pre-scaled by 1/sqrt(dk), tf32-rounded)
#pragma unroll
    for (int i = 0; i < 8; i++) {
        int e = i * 128 + tid;
        int r = e >> 4, c = (e & 15) << 2;
        float4 v = *(const float4*)&Qg[(size_t)(qb * 64 + r) * DK + c];
        float4 o;
        o.x = f2tff(v.x * 0.125f); o.y = f2tff(v.y * 0.125f);
        o.z = f2tff(v.z * 0.125f); o.w = f2tff(v.w * 0.125f);
        *(float4*)&sQP[r * 72 + c] = o;
    }
    __syncthreads();

    // hoist Q fragments into registers (8 k-steps x 4 regs)
    const int qr = w * 16 + g;
    unsigned qf[8][4];
#pragma unroll
    for (int ks = 0; ks < 8; ks++) {
        const float* p = &sQP[qr * 72 + ks * 8 + t];
        qf[ks][0] = __float_as_uint(p[0]);
        qf[ks][1] = __float_as_uint(p[8 * 72]);
        qf[ks][2] = __float_as_uint(p[4]);
        qf[ks][3] = __float_as_uint(p[8 * 72 + 4]);
    }
    __syncthreads();

    float mrun[2] = {-1e30f, -1e30f};
    float lrun[2] = {0.f, 0.f};
    float oacc[8][4];
#pragma unroll
    for (int nt = 0; nt < 8; nt++)
#pragma unroll
        for (int k = 0; k < 4; k++) oacc[nt][k] = 0.f;

    for (int kb = 0; kb <= qb; kb++) {
        // batch LDGs first (overlap memory latency with barrier skew)
        float4 kk[8], vv[8];
#pragma unroll
        for (int i = 0; i < 8; i++) {
            int e = i * 128 + tid;
            int r = e >> 4, c = (e & 15) << 2;
            kk[i] = *(const float4*)&Kg[(size_t)(kb * 64 + r) * DK + c];
            vv[i] = *(const float4*)&Vg[(size_t)(kb * 64 + r) * DK + c];
        }
        __syncthreads();   // previous iter's sK/sV reads complete
#pragma unroll
        for (int i = 0; i < 8; i++) {
            int e = i * 128 + tid;
            int r = e >> 4, c = (e & 15) << 2;
            float4 ko, vo;
            ko.x = f2tff(kk[i].x); ko.y = f2tff(kk[i].y); ko.z = f2tff(kk[i].z); ko.w = f2tff(kk[i].w);
            vo.x = f2tff(vv[i].x); vo.y = f2tff(vv[i].y); vo.z = f2tff(vv[i].z); vo.w = f2tff(vv[i].w);
            *(float4*)&sK[r * 68 + c] = ko;
            *(float4*)&sV[r * 72 + c] = vo;
        }
        __syncthreads();

        // S = Q K^T : warp tile 16x64, 8 n-tiles x 8 k-steps
        float s[8][4];
#pragma unroll
        for (int nt = 0; nt < 8; nt++)
#pragma unroll
            for (int k = 0; k < 4; k++) s[nt][k] = 0.f;

#pragma unroll
        for (int ks = 0; ks < 8; ks++) {
#pragma unroll
            for (int nt = 0; nt < 8; nt++) {
                unsigned kf[2];
                const float* p = &sK[(nt * 8 + g) * 68 + ks * 8 + t];
                kf[0] = __float_as_uint(p[0]);
                kf[1] = __float_as_uint(p[4]);
                mma8(s[nt], qf[ks], kf);
            }
        }

        // causal mask on diagonal block
        if (kb == qb) {
#pragma unroll
            for (int nt = 0; nt < 8; nt++) {
                int col = nt * 8 + 2 * t;
                if (col     > qr)     s[nt][0] = -1e30f;
                if (col + 1 > qr)     s[nt][1] = -1e30f;
                if (col     > qr + 8) s[nt][2] = -1e30f;
                if (col + 1 > qr + 8) s[nt][3] = -1e30f;
            }
        }

        __syncwarp();   // prior PV reads of sP done before overwrite

        // online softmax: 2 rows per thread (qr, qr+8); row group = 4 lanes
#pragma unroll
        for (int r = 0; r < 2; r++) {
            float mx = -1e30f;
#pragma unroll
            for (int nt = 0; nt < 8; nt++)
                mx = fmaxf(mx, fmaxf(s[nt][2*r], s[nt][2*r + 1]));
            mx = fmaxf(mx, __shfl_xor_sync(0xffffffffu, mx, 1));
            mx = fmaxf(mx, __shfl_xor_sync(0xffffffffu, mx, 2));
            float mnew = fmaxf(mrun[r], mx);
            float corr = __expf(mrun[r] - mnew);
            float rs = 0.f;
            float* prow = &sQP[(qr + 8 * r) * 72];
#pragma unroll
            for (int nt = 0; nt < 8; nt++) {
                float p0 = __expf(s[nt][2*r]     - mnew);
                float p1 = __expf(s[nt][2*r + 1] - mnew);
                rs += p0 + p1;
                *(float2*)&prow[nt * 8 + 2 * t] = make_float2(f2tff(p0), f2tff(p1));
            }
            rs += __shfl_xor_sync(0xffffffffu, rs, 1);
            rs += __shfl_xor_sync(0xffffffffu, rs, 2);
            lrun[r] = lrun[r] * corr + rs;
            mrun[r] = mnew;
#pragma unroll
            for (int nt = 0; nt < 8; nt++) {
                oacc[nt][2*r]     *= corr;
                oacc[nt][2*r + 1] *= corr;
            }
        }
        __syncwarp();

        // O += P V : 8 k-steps over kpos, 8 n-tiles over dk
#pragma unroll
        for (int ks = 0; ks < 8; ks++) {
            unsigned pf[4];
            const float* pp = &sQP[qr * 72 + ks * 8 + t];
            pf[0] = __float_as_uint(pp[0]);
            pf[1] = __float_as_uint(pp[8 * 72]);
            pf[2] = __float_as_uint(pp[4]);
            pf[3] = __float_as_uint(pp[8 * 72 + 4]);
#pragma unroll
            for (int nt = 0; nt < 8; nt++) {
                unsigned vf[2];
                const float* vp = &sV[(ks * 8 + t) * 72 + nt * 8 + g];
                vf[0] = __float_as_uint(vp[0]);
                vf[1] = __float_as_uint(vp[4 * 72]);
                mma8(oacc[nt], pf, vf);
            }
        }
    }

    // epilogue: normalize, scatter to [B,S,D]
    const int b = bh >> 4;
    const int h = bh & 15;
#pragma unroll
    for (int r = 0; r < 2; r++) {
        float inv = 1.f / lrun[r];
        int q = qb * 64 + qr + 8 * r;
        float* dst = &g_O[((size_t)b * SSZ + q) * DSZ + h * DK];
#pragma unroll
        for (int nt = 0; nt < 8; nt++)
            *(float2*)&dst[nt * 8 + 2 * t] =
                make_float2(oacc[nt][2*r] * inv, oacc[nt][2*r + 1] * inv);
    }
}

// ---------------------------------------------------------------------------
extern "C" void kernel_launch(void* const* d_in, const int* in_sizes, int n_in,
                              void* d_out, int out_size) {
    (void)in_sizes; (void)n_in; (void)out_size;
    const float* x  = (const float*)d_in[0];
    const float* Wq = (const float*)d_in[1];
    const float* Wk = (const float*)d_in[2];
    const float* Wv = (const float*)d_in[3];
    const float* Wo = (const float*)d_in[4];
    float* out = (float*)d_out;

    rope_table_kernel<<<(SSZ * NPAIR + 255) / 256, 256>>>();
    gemm_qkv_kernel<<<dim3(8, 32, 3), 256>>>(x, Wq, Wk, Wv);
    rope_apply_kernel<<<(BSZ * HN * SSZ * NPAIR + 255) / 256, 256>>>();

    const int attn_smem = (64*72 + 64*68 + 64*72) * (int)sizeof(float);  // 54272 B
    cudaFuncSetAttribute(attn_kernel, cudaFuncAttributeMaxDynamicSharedMemorySize, attn_smem);
    attn_kernel<<<dim3(SSZ / 64, BSZ * HN), 128, attn_smem>>>();

    gemm_out_kernel<<<dim3(8, 32), 256>>>(Wo, out);
}